// round 1
// baseline (speedup 1.0000x reference)
#include <cuda_runtime.h>

#define IN_DIM   1024
#define OUT_DIM  65536
#define BATCH    32
#define NPAIR    16      // 32 batch rows packed as 16 f32x2 pairs
#define KT       128     // k-chunk staged in shared
#define THREADS  128
#define NC       2       // output columns per thread

__device__ __forceinline__ unsigned long long pack2(float lo, float hi) {
    unsigned long long r;
    asm("mov.b64 %0, {%1, %2};" : "=l"(r) : "f"(lo), "f"(hi));
    return r;
}

__device__ __forceinline__ void unpack2(unsigned long long v, float& lo, float& hi) {
    asm("mov.b64 {%0, %1}, %2;" : "=f"(lo), "=f"(hi) : "l"(v));
}

// d = a * b + d  (packed 2x fp32, Blackwell FFMA2 — only reachable via PTX)
__device__ __forceinline__ void ffma2(unsigned long long& d,
                                      unsigned long long a,
                                      unsigned long long b) {
    asm("fma.rn.f32x2 %0, %1, %2, %3;" : "=l"(d) : "l"(a), "l"(b), "l"(d));
}

__global__ __launch_bounds__(THREADS)
void sparse_linear_kernel(const float* __restrict__ x,
                          const float* __restrict__ mask,
                          const float* __restrict__ w,
                          const float* __restrict__ bias,
                          float* __restrict__ out)
{
    // xs[k][p] = (x[2p][kc+k], x[2p+1][kc+k]) packed as f32x2
    __shared__ unsigned long long xs[KT][NPAIR];

    const int col0 = (blockIdx.x * THREADS + threadIdx.x) * NC;

    unsigned long long acc[NPAIR][NC];
#pragma unroll
    for (int p = 0; p < NPAIR; p++)
#pragma unroll
        for (int c = 0; c < NC; c++)
            acc[p][c] = 0ULL;

    for (int kc = 0; kc < IN_DIM; kc += KT) {
        // Cooperatively stage the x chunk, pre-paired over batch.
        for (int idx = threadIdx.x; idx < KT * NPAIR; idx += THREADS) {
            int k = idx / NPAIR;
            int p = idx % NPAIR;
            float lo = x[(size_t)(2 * p)     * IN_DIM + kc + k];
            float hi = x[(size_t)(2 * p + 1) * IN_DIM + kc + k];
            xs[k][p] = pack2(lo, hi);
        }
        __syncthreads();

#pragma unroll 4
        for (int k = 0; k < KT; k++) {
            const size_t rowbase = (size_t)(kc + k) * OUT_DIM + col0;
            const float2 wv = *reinterpret_cast<const float2*>(w    + rowbase);
            const float2 mv = *reinterpret_cast<const float2*>(mask + rowbase);
            const float m0 = wv.x * mv.x;
            const float m1 = wv.y * mv.y;
            const unsigned long long bb0 = pack2(m0, m0);
            const unsigned long long bb1 = pack2(m1, m1);
#pragma unroll
            for (int p = 0; p < NPAIR; p++) {
                const unsigned long long xv = xs[k][p];
                ffma2(acc[p][0], xv, bb0);
                ffma2(acc[p][1], xv, bb1);
            }
        }
        __syncthreads();
    }

    // Epilogue: out[b][col0..col0+1] per batch row, float2 stores.
    const float bias0 = bias[col0];
    const float bias1 = bias[col0 + 1];
#pragma unroll
    for (int p = 0; p < NPAIR; p++) {
        float a0lo, a0hi, a1lo, a1hi;
        unpack2(acc[p][0], a0lo, a0hi);   // (batch 2p, batch 2p+1) for col0
        unpack2(acc[p][1], a1lo, a1hi);   // (batch 2p, batch 2p+1) for col0+1
        float2 r_even = make_float2(a0lo + bias0, a1lo + bias1);
        float2 r_odd  = make_float2(a0hi + bias0, a1hi + bias1);
        *reinterpret_cast<float2*>(out + (size_t)(2 * p)     * OUT_DIM + col0) = r_even;
        *reinterpret_cast<float2*>(out + (size_t)(2 * p + 1) * OUT_DIM + col0) = r_odd;
    }
}

extern "C" void kernel_launch(void* const* d_in, const int* in_sizes, int n_in,
                              void* d_out, int out_size) {
    const float* x    = (const float*)d_in[0];
    const float* mask = (const float*)d_in[1];
    const float* w    = (const float*)d_in[2];
    const float* bias = (const float*)d_in[3];
    float* out = (float*)d_out;

    const int total_threads = OUT_DIM / NC;            // 32768
    const int blocks = total_threads / THREADS;        // 256
    sparse_linear_kernel<<<blocks, THREADS>>>(x, mask, w, bias, out);
}

// round 2
// speedup vs baseline: 3.0632x; 3.0632x over previous
#include <cuda_runtime.h>

#define IN_DIM   1024
#define OUT_DIM  65536
#define BATCH    32
#define NPAIR    16      // 32 batch rows packed as 16 f32x2 pairs
#define NC       2       // output columns per thread
#define THREADS  128
#define KSPLIT   4
#define KS       (IN_DIM / KSPLIT)   // 256 k-values per block
#define UNROLL   4

// Partial sums: [split][batch][out]  (33.5 MB scratch, no allocation allowed)
__device__ float g_partial[KSPLIT * BATCH * OUT_DIM];

__device__ __forceinline__ unsigned long long pack2(float lo, float hi) {
    unsigned long long r;
    asm("mov.b64 %0, {%1, %2};" : "=l"(r) : "f"(lo), "f"(hi));
    return r;
}

__device__ __forceinline__ void unpack2(unsigned long long v, float& lo, float& hi) {
    asm("mov.b64 {%0, %1}, %2;" : "=f"(lo), "=f"(hi) : "l"(v));
}

// d = a * b + d  (packed 2x fp32 FFMA2 — PTX-only)
__device__ __forceinline__ void ffma2(unsigned long long& d,
                                      unsigned long long a,
                                      unsigned long long b) {
    asm("fma.rn.f32x2 %0, %1, %2, %3;" : "=l"(d) : "l"(a), "l"(b), "l"(d));
}

__global__ __launch_bounds__(THREADS, 4)
void sparse_linear_main(const float* __restrict__ x,
                        const float* __restrict__ mask,
                        const float* __restrict__ w)
{
    // xs[k][p] = (x[2p][kbase+k], x[2p+1][kbase+k]) packed as f32x2
    __shared__ unsigned long long xs[KS][NPAIR];   // 32 KB

    const int split = blockIdx.y;
    const int kbase = split * KS;
    const int col0  = (blockIdx.x * THREADS + threadIdx.x) * NC;

    // Stage this split's x slice once (single barrier for the whole kernel).
    for (int idx = threadIdx.x; idx < KS * NPAIR; idx += THREADS) {
        int k = idx / NPAIR;
        int p = idx % NPAIR;
        float lo = x[(size_t)(2 * p)     * IN_DIM + kbase + k];
        float hi = x[(size_t)(2 * p + 1) * IN_DIM + kbase + k];
        xs[k][p] = pack2(lo, hi);
    }
    __syncthreads();

    unsigned long long acc[NPAIR][NC];
#pragma unroll
    for (int p = 0; p < NPAIR; p++)
#pragma unroll
        for (int c = 0; c < NC; c++)
            acc[p][c] = 0ULL;

    for (int k = 0; k < KS; k += UNROLL) {
        // Front-batch the global loads: 2*UNROLL outstanding 256B warp-loads.
        float2 wv[UNROLL], mv[UNROLL];
#pragma unroll
        for (int u = 0; u < UNROLL; u++) {
            const size_t rowbase = (size_t)(kbase + k + u) * OUT_DIM + col0;
            wv[u] = *reinterpret_cast<const float2*>(w    + rowbase);
            mv[u] = *reinterpret_cast<const float2*>(mask + rowbase);
        }
#pragma unroll
        for (int u = 0; u < UNROLL; u++) {
            const float m0 = wv[u].x * mv[u].x;
            const float m1 = wv[u].y * mv[u].y;
            const unsigned long long bb0 = pack2(m0, m0);
            const unsigned long long bb1 = pack2(m1, m1);
            const ulonglong2* xr = reinterpret_cast<const ulonglong2*>(&xs[k + u][0]);
#pragma unroll
            for (int q = 0; q < NPAIR / 2; q++) {
                const ulonglong2 xv = xr[q];          // LDS.128: pairs 2q, 2q+1
                ffma2(acc[2 * q][0],     xv.x, bb0);
                ffma2(acc[2 * q][1],     xv.x, bb1);
                ffma2(acc[2 * q + 1][0], xv.y, bb0);
                ffma2(acc[2 * q + 1][1], xv.y, bb1);
            }
        }
    }

    // Write partials (bias added in reduce kernel).
    float* part = g_partial + (size_t)split * BATCH * OUT_DIM;
#pragma unroll
    for (int p = 0; p < NPAIR; p++) {
        float a0lo, a0hi, a1lo, a1hi;
        unpack2(acc[p][0], a0lo, a0hi);   // (batch 2p, 2p+1) for col0
        unpack2(acc[p][1], a1lo, a1hi);   // (batch 2p, 2p+1) for col0+1
        *reinterpret_cast<float2*>(part + (size_t)(2 * p)     * OUT_DIM + col0) =
            make_float2(a0lo, a1lo);
        *reinterpret_cast<float2*>(part + (size_t)(2 * p + 1) * OUT_DIM + col0) =
            make_float2(a0hi, a1hi);
    }
}

__global__ __launch_bounds__(256)
void sparse_linear_reduce(const float* __restrict__ bias, float* __restrict__ out)
{
    const size_t i = (size_t)blockIdx.x * blockDim.x + threadIdx.x;  // float4 index
    const size_t elem = i * 4;
    const int col = (int)(elem % OUT_DIM);

    float4 s = *reinterpret_cast<const float4*>(g_partial + elem);
#pragma unroll
    for (int sp = 1; sp < KSPLIT; sp++) {
        const float4 v = *reinterpret_cast<const float4*>(
            g_partial + (size_t)sp * BATCH * OUT_DIM + elem);
        s.x += v.x; s.y += v.y; s.z += v.z; s.w += v.w;
    }
    const float4 bv = *reinterpret_cast<const float4*>(bias + col);
    s.x += bv.x; s.y += bv.y; s.z += bv.z; s.w += bv.w;
    *reinterpret_cast<float4*>(out + elem) = s;
}

extern "C" void kernel_launch(void* const* d_in, const int* in_sizes, int n_in,
                              void* d_out, int out_size) {
    const float* x    = (const float*)d_in[0];
    const float* mask = (const float*)d_in[1];
    const float* w    = (const float*)d_in[2];
    const float* bias = (const float*)d_in[3];
    float* out = (float*)d_out;

    dim3 grid(OUT_DIM / NC / THREADS, KSPLIT);   // (256, 4)
    sparse_linear_main<<<grid, THREADS>>>(x, mask, w);

    const int total4 = BATCH * OUT_DIM / 4;      // 524288
    sparse_linear_reduce<<<total4 / 256, 256>>>(bias, out);
}

// round 3
// speedup vs baseline: 3.4085x; 1.1127x over previous
#include <cuda_runtime.h>

#define IN_DIM   1024
#define OUT_DIM  65536
#define BATCH    32
#define NPAIR    16      // 32 batch rows packed as 16 f32x2 pairs
#define NC       2       // output columns per thread
#define THREADS  128
#define KSPLIT   4
#define KS       (IN_DIM / KSPLIT)   // 256 k-values per block
#define UNROLL   4
#define NGROUPS  (KS / UNROLL)       // 64

// Partial sums: [split][batch][out]  (33.5 MB scratch; fits in L2 for reduce)
__device__ float g_partial[KSPLIT * BATCH * OUT_DIM];

__device__ __forceinline__ unsigned long long pack2(float lo, float hi) {
    unsigned long long r;
    asm("mov.b64 %0, {%1, %2};" : "=l"(r) : "f"(lo), "f"(hi));
    return r;
}

__device__ __forceinline__ void unpack2(unsigned long long v, float& lo, float& hi) {
    asm("mov.b64 {%0, %1}, %2;" : "=f"(lo), "=f"(hi) : "l"(v));
}

// d = a * b + d  (packed 2x fp32 FFMA2 — PTX-only)
__device__ __forceinline__ void ffma2(unsigned long long& d,
                                      unsigned long long a,
                                      unsigned long long b) {
    asm("fma.rn.f32x2 %0, %1, %2, %3;" : "=l"(d) : "l"(a), "l"(b), "l"(d));
}

__global__ __launch_bounds__(THREADS, 4)
void sparse_linear_main(const float* __restrict__ x,
                        const float* __restrict__ mask,
                        const float* __restrict__ w)
{
    // xs[k][p] = (x[2p][kbase+k], x[2p+1][kbase+k]) packed as f32x2
    __shared__ alignas(16) unsigned long long xs[KS][NPAIR];   // 32 KB

    const int split = blockIdx.y;
    const int kbase = split * KS;
    const int col0  = (blockIdx.x * THREADS + threadIdx.x) * NC;

    // Stage this split's x slice once (single barrier for the whole kernel).
    for (int idx = threadIdx.x; idx < KS * NPAIR; idx += THREADS) {
        int k = idx / NPAIR;
        int p = idx % NPAIR;
        float lo = x[(size_t)(2 * p)     * IN_DIM + kbase + k];
        float hi = x[(size_t)(2 * p + 1) * IN_DIM + kbase + k];
        xs[k][p] = pack2(lo, hi);
    }
    __syncthreads();

    unsigned long long acc[NPAIR][NC];
#pragma unroll
    for (int p = 0; p < NPAIR; p++)
#pragma unroll
        for (int c = 0; c < NC; c++)
            acc[p][c] = 0ULL;

    const float* wbase = w    + (size_t)kbase * OUT_DIM + col0;
    const float* mbase = mask + (size_t)kbase * OUT_DIM + col0;

    float2 wA[UNROLL], mA[UNROLL], wB[UNROLL], mB[UNROLL];

#define LOAD_GROUP(WB, MB, G)                                                   \
    {                                                                           \
        _Pragma("unroll")                                                       \
        for (int u = 0; u < UNROLL; u++) {                                      \
            const size_t off = (size_t)((G) * UNROLL + u) * OUT_DIM;            \
            (WB)[u] = *reinterpret_cast<const float2*>(wbase + off);            \
            (MB)[u] = *reinterpret_cast<const float2*>(mbase + off);            \
        }                                                                       \
    }

#define COMPUTE_GROUP(WB, MB, G)                                                \
    {                                                                           \
        _Pragma("unroll")                                                       \
        for (int u = 0; u < UNROLL; u++) {                                      \
            const float m0 = (WB)[u].x * (MB)[u].x;                             \
            const float m1 = (WB)[u].y * (MB)[u].y;                             \
            const unsigned long long bb0 = pack2(m0, m0);                       \
            const unsigned long long bb1 = pack2(m1, m1);                       \
            const ulonglong2* xr =                                              \
                reinterpret_cast<const ulonglong2*>(&xs[(G) * UNROLL + u][0]);  \
            _Pragma("unroll")                                                   \
            for (int q = 0; q < NPAIR / 2; q++) {                               \
                const ulonglong2 xv = xr[q];                                    \
                ffma2(acc[2 * q][0],     xv.x, bb0);                            \
                ffma2(acc[2 * q][1],     xv.x, bb1);                            \
                ffma2(acc[2 * q + 1][0], xv.y, bb0);                            \
                ffma2(acc[2 * q + 1][1], xv.y, bb1);                            \
            }                                                                   \
        }                                                                       \
    }

    // Software pipeline, 2-deep register double buffer, two groups per iter.
    LOAD_GROUP(wA, mA, 0);
#pragma unroll 1
    for (int g = 0; g < NGROUPS; g += 2) {
        LOAD_GROUP(wB, mB, g + 1);
        COMPUTE_GROUP(wA, mA, g);
        if (g + 2 < NGROUPS) LOAD_GROUP(wA, mA, g + 2);
        COMPUTE_GROUP(wB, mB, g + 1);
    }

#undef LOAD_GROUP
#undef COMPUTE_GROUP

    // Write partials (bias added in reduce kernel).
    float* part = g_partial + (size_t)split * BATCH * OUT_DIM;
#pragma unroll
    for (int p = 0; p < NPAIR; p++) {
        float a0lo, a0hi, a1lo, a1hi;
        unpack2(acc[p][0], a0lo, a0hi);   // (batch 2p, 2p+1) for col0
        unpack2(acc[p][1], a1lo, a1hi);   // (batch 2p, 2p+1) for col0+1
        *reinterpret_cast<float2*>(part + (size_t)(2 * p)     * OUT_DIM + col0) =
            make_float2(a0lo, a1lo);
        *reinterpret_cast<float2*>(part + (size_t)(2 * p + 1) * OUT_DIM + col0) =
            make_float2(a0hi, a1hi);
    }
}

__global__ __launch_bounds__(256)
void sparse_linear_reduce(const float* __restrict__ bias, float* __restrict__ out)
{
    const size_t i = (size_t)blockIdx.x * blockDim.x + threadIdx.x;  // float4 index
    const size_t elem = i * 4;
    const int col = (int)(elem % OUT_DIM);

    float4 s = *reinterpret_cast<const float4*>(g_partial + elem);
#pragma unroll
    for (int sp = 1; sp < KSPLIT; sp++) {
        const float4 v = *reinterpret_cast<const float4*>(
            g_partial + (size_t)sp * BATCH * OUT_DIM + elem);
        s.x += v.x; s.y += v.y; s.z += v.z; s.w += v.w;
    }
    const float4 bv = *reinterpret_cast<const float4*>(bias + col);
    s.x += bv.x; s.y += bv.y; s.z += bv.z; s.w += bv.w;
    *reinterpret_cast<float4*>(out + elem) = s;
}

extern "C" void kernel_launch(void* const* d_in, const int* in_sizes, int n_in,
                              void* d_out, int out_size) {
    const float* x    = (const float*)d_in[0];
    const float* mask = (const float*)d_in[1];
    const float* w    = (const float*)d_in[2];
    const float* bias = (const float*)d_in[3];
    float* out = (float*)d_out;

    dim3 grid(OUT_DIM / NC / THREADS, KSPLIT);   // (256, 4)
    sparse_linear_main<<<grid, THREADS>>>(x, mask, w);

    const int total4 = BATCH * OUT_DIM / 4;      // 524288
    sparse_linear_reduce<<<total4 / 256, 256>>>(bias, out);
}